// round 16
// baseline (speedup 1.0000x reference)
#include <cuda_runtime.h>
#include <cuda_fp16.h>
#include <mma.h>

using namespace nvcuda;

#define B_  4
#define S_  2048
#define E_  1024
#define H_  16
#define DH_ 64
#define BS_ (B_*S_)   // 8192

// Scratch (allocation-free rule: __device__ globals)
__device__ __half g_q[H_*BS_*DH_];       // Q pre-scaled by 1/8
__device__ __half g_k[H_*BS_*DH_];
__device__ __half g_v[H_*BS_*DH_];
__device__ __half g_concat[BS_*E_];      // [b,s, h*64+d]

typedef wmma::fragment<wmma::matrix_a, 16,16,16, __half, wmma::row_major> HFragA;
typedef wmma::fragment<wmma::matrix_b, 16,16,16, __half, wmma::col_major> HFragBc;
typedef wmma::fragment<wmma::matrix_b, 16,16,16, __half, wmma::row_major> HFragBr;
typedef wmma::fragment<wmma::accumulator, 16,16,16, float> HFragC;

__device__ __forceinline__ void st_half4(__half* dst, float4 v) {
    *(half2*)dst       = __floats2half2_rn(v.x, v.y);
    *(half2*)(dst + 2) = __floats2half2_rn(v.z, v.w);
}

// ---------------------------------------------------------------------------
// K1: merged QKV projection (fp16 HMMA).  M-tile 128 (halves W L2 traffic),
// 512 threads = 16 warps (8m x 2n), warp tile 16x32, 3 outputs (q,k,v).
// grid (BS/128, H), block 512.  K-chunk 64.
// ---------------------------------------------------------------------------
__global__ void qkv_tc_kernel(const float* __restrict__ hs,
                              const float* __restrict__ Wq, const float* __restrict__ bq,
                              const float* __restrict__ Wk, const float* __restrict__ bk,
                              const float* __restrict__ Wv, const float* __restrict__ bv) {
    const int h  = blockIdx.y;
    const int m0 = blockIdx.x * 128;
    const float* Wz[3] = { Wq + (size_t)h * E_ * DH_,
                           Wk + (size_t)h * E_ * DH_,
                           Wv + (size_t)h * E_ * DH_ };
    const float* bz[3] = { bq + h * DH_, bk + h * DH_, bv + h * DH_ };
    __half* oz[3] = { g_q + (size_t)h * BS_ * DH_ + (size_t)m0 * DH_,
                      g_k + (size_t)h * BS_ * DH_ + (size_t)m0 * DH_,
                      g_v + (size_t)h * BS_ * DH_ + (size_t)m0 * DH_ };

    // [0,18432) As half[128][72]; [18432 + z*9216) Bs[z] half[64][72]
    // epilogue: St float[128][68] = 34816 B (aliases whole buffer)
    __shared__ __align__(16) unsigned char smbuf[46080];
    __half (*As)[72] = (__half(*)[72])smbuf;
    float  (*St)[68] = (float(*)[68])smbuf;

    const int tid  = threadIdx.x;
    const int warp = tid >> 5;
    const int wm = warp >> 1, wn = warp & 1;   // 8 m-slots x 2 n-slots

    HFragC acc[3][2];
    #pragma unroll
    for (int z = 0; z < 3; z++) {
        wmma::fill_fragment(acc[z][0], 0.f);
        wmma::fill_fragment(acc[z][1], 0.f);
    }

    for (int k0 = 0; k0 < E_; k0 += 64) {
        #pragma unroll
        for (int i = 0; i < 4; i++) {                 // As: 128x64 = 2048 float4
            const int vi = tid + i * 512;
            const int r = vi >> 4, c = (vi & 15) * 4;
            st_half4(&As[r][c], *(const float4*)&hs[(size_t)(m0 + r) * E_ + k0 + c]);
        }
        #pragma unroll
        for (int z = 0; z < 3; z++) {                 // Bs[z]: 64x64 = 1024 float4
            __half (*Bs)[72] = (__half(*)[72])(smbuf + 18432 + z * 9216);
            #pragma unroll
            for (int i = 0; i < 2; i++) {
                const int vi = tid + i * 512;
                const int r = vi >> 4, c = (vi & 15) * 4;
                st_half4(&Bs[r][c], *(const float4*)&Wz[z][(size_t)(k0 + r) * DH_ + c]);
            }
        }
        __syncthreads();
        #pragma unroll
        for (int kk = 0; kk < 64; kk += 16) {
            HFragA a; wmma::load_matrix_sync(a, &As[wm*16][kk], 72);
            #pragma unroll
            for (int z = 0; z < 3; z++) {
                __half (*Bs)[72] = (__half(*)[72])(smbuf + 18432 + z * 9216);
                HFragBr b0; wmma::load_matrix_sync(b0, &Bs[kk][wn*32], 72);
                wmma::mma_sync(acc[z][0], a, b0, acc[z][0]);
                HFragBr b1; wmma::load_matrix_sync(b1, &Bs[kk][wn*32 + 16], 72);
                wmma::mma_sync(acc[z][1], a, b1, acc[z][1]);
            }
        }
        __syncthreads();
    }
    #pragma unroll
    for (int z = 0; z < 3; z++) {
        const float out_scale = (z == 0) ? 0.125f : 1.0f;
        wmma::store_matrix_sync(&St[wm*16][wn*32],      acc[z][0], 68, wmma::mem_row_major);
        wmma::store_matrix_sync(&St[wm*16][wn*32 + 16], acc[z][1], 68, wmma::mem_row_major);
        __syncthreads();
        const float* bias = bz[z];
        #pragma unroll
        for (int i = 0; i < 4; i++) {                 // 128x64 = 2048 float4
            const int vi = tid + i * 512;
            const int r = vi >> 4, c = (vi & 15) * 4;
            float4 s = *(float4*)&St[r][c];
            s.x = (s.x + bias[c])   * out_scale;
            s.y = (s.y + bias[c+1]) * out_scale;
            s.z = (s.z + bias[c+2]) * out_scale;
            s.w = (s.w + bias[c+3]) * out_scale;
            st_half4(&oz[z][(size_t)r * DH_ + c], s);
        }
        __syncthreads();
    }
}

// ---------------------------------------------------------------------------
// K2: two-pass attention (fp16 HMMA), KV-tile 64, parallel electrode.
// Pass 1: stream K, S = QK^T, row-sum of exp(S) -> 1/l.
// Pass 2: recompute S, write NORMALIZED exp(S)/l (fp32) to weights,
//         electrode via shfl + red[8][64] + 64-thread atomics, PV accumulate.
// grid (S/64, H*B), block 256 (8 warps: 4m x 2n, warp 16x32).
// ---------------------------------------------------------------------------
__global__ void attn_fused_kernel(float* __restrict__ wts, float* __restrict__ elect) {
    const int hb = blockIdx.y;
    const int h = hb / B_, b = hb % B_;
    const int m0 = blockIdx.x * 64;
    const __half* q = g_q + ((size_t)h * BS_ + (size_t)b * S_) * DH_;
    const __half* k = g_k + ((size_t)h * BS_ + (size_t)b * S_) * DH_;
    const __half* v = g_v + ((size_t)h * BS_ + (size_t)b * S_) * DH_;
    float* w = wts + (size_t)hb * S_ * S_;

    // [0,17408)      Qs half[64][72] (9216) -> Ss float[64][68] -> St epilogue
    // [17408,26624)  Ks half[64][72]
    // [26624,35840)  Vs half[64][72]
    // [35840,45056)  Ps half[64][72]
    __shared__ __align__(16) unsigned char smbuf[45056];
    __half (*Qs)[72] = (__half(*)[72])smbuf;
    float  (*Ss)[68] = (float(*)[68])smbuf;
    __half (*Ks)[72] = (__half(*)[72])(smbuf + 17408);
    __half (*Vs)[72] = (__half(*)[72])(smbuf + 26624);
    __half (*Ps)[72] = (__half(*)[72])(smbuf + 35840);
    float  (*St)[68] = (float(*)[68])smbuf;
    __shared__ float red[8][64];
    __shared__ float l_s[64];

    const int tid  = threadIdx.x;
    const int warp = tid >> 5;
    const int wm = warp >> 1, wn = warp & 1;

    // load Q tile (pre-scaled by 1/8)
    #pragma unroll
    for (int i = 0; i < 4; i++) {
        const int vi = tid + i * 256;
        const int r = vi >> 4, c = (vi & 15) * 4;
        *(uint2*)&Qs[r][c] = *(const uint2*)&q[(size_t)(m0 + r) * DH_ + c];
    }
    __syncthreads();

    HFragA qa[4];
    #pragma unroll
    for (int kk = 0; kk < 4; kk++)
        wmma::load_matrix_sync(qa[kk], &Qs[wm*16][kk*16], 72);
    __syncthreads();   // Qs free -> Ss

    const int row = tid >> 2, qd = tid & 3;   // 64 rows x 4 lanes (16 cols each)
    float lsum = 0.f;

    // ===================== pass 1: row sums of exp(S) =====================
    for (int t0 = 0; t0 < S_; t0 += 64) {
        #pragma unroll
        for (int i = 0; i < 4; i++) {
            const int vi = tid + i * 256;
            const int r = vi >> 4, c = (vi & 15) * 4;
            *(uint2*)&Ks[r][c] = *(const uint2*)&k[(size_t)(t0 + r) * DH_ + c];
        }
        __syncthreads();

        HFragC c0, c1;
        wmma::fill_fragment(c0, 0.f);
        wmma::fill_fragment(c1, 0.f);
        #pragma unroll
        for (int kk = 0; kk < 4; kk++) {
            HFragBc b0; wmma::load_matrix_sync(b0, &Ks[wn*32][kk*16], 72);
            wmma::mma_sync(c0, qa[kk], b0, c0);
            HFragBc b1; wmma::load_matrix_sync(b1, &Ks[wn*32 + 16][kk*16], 72);
            wmma::mma_sync(c1, qa[kk], b1, c1);
        }
        wmma::store_matrix_sync(&Ss[wm*16][wn*32],      c0, 68, wmma::mem_row_major);
        wmma::store_matrix_sync(&Ss[wm*16][wn*32 + 16], c1, 68, wmma::mem_row_major);
        __syncthreads();

        #pragma unroll
        for (int jj = 0; jj < 4; jj++) {
            float4 sv = *(float4*)&Ss[row][qd*16 + jj*4];
            lsum += __expf(sv.x) + __expf(sv.y) + __expf(sv.z) + __expf(sv.w);
        }
    }
    lsum += __shfl_xor_sync(0xffffffffu, lsum, 1);
    lsum += __shfl_xor_sync(0xffffffffu, lsum, 2);
    if (qd == 0) l_s[row] = 1.0f / lsum;
    __syncthreads();
    const float il = l_s[row];

    // ===================== pass 2: normalized P + electrode + PV ==========
    HFragC pv0, pv1;
    wmma::fill_fragment(pv0, 0.f);
    wmma::fill_fragment(pv1, 0.f);

    const float esc = 1.0f / (H_ * S_);

    for (int t0 = 0; t0 < S_; t0 += 64) {
        #pragma unroll
        for (int i = 0; i < 4; i++) {
            const int vi = tid + i * 256;
            const int r = vi >> 4, c = (vi & 15) * 4;
            *(uint2*)&Ks[r][c] = *(const uint2*)&k[(size_t)(t0 + r) * DH_ + c];
            *(uint2*)&Vs[r][c] = *(const uint2*)&v[(size_t)(t0 + r) * DH_ + c];
        }
        __syncthreads();

        HFragC c0, c1;
        wmma::fill_fragment(c0, 0.f);
        wmma::fill_fragment(c1, 0.f);
        #pragma unroll
        for (int kk = 0; kk < 4; kk++) {
            HFragBc b0; wmma::load_matrix_sync(b0, &Ks[wn*32][kk*16], 72);
            wmma::mma_sync(c0, qa[kk], b0, c0);
            HFragBc b1; wmma::load_matrix_sync(b1, &Ks[wn*32 + 16][kk*16], 72);
            wmma::mma_sync(c1, qa[kk], b1, c1);
        }
        wmma::store_matrix_sync(&Ss[wm*16][wn*32],      c0, 68, wmma::mem_row_major);
        wmma::store_matrix_sync(&Ss[wm*16][wn*32 + 16], c1, 68, wmma::mem_row_major);
        __syncthreads();

        // normalized p (fp32): write weights, half to Ps, electrode partials
        {
            float p[16];
            float* wr = &w[(size_t)(m0 + row) * S_ + t0 + qd*16];
            #pragma unroll
            for (int jj = 0; jj < 4; jj++) {
                float4 sv = *(float4*)&Ss[row][qd*16 + jj*4];
                sv.x = __expf(sv.x) * il;  sv.y = __expf(sv.y) * il;
                sv.z = __expf(sv.z) * il;  sv.w = __expf(sv.w) * il;
                p[jj*4+0] = sv.x; p[jj*4+1] = sv.y; p[jj*4+2] = sv.z; p[jj*4+3] = sv.w;
                *(float4*)(wr + jj*4) = sv;
                st_half4(&Ps[row][qd*16 + jj*4], sv);
            }
            // electrode: sum over this warp's 8 rows (lanes stride 4 share qd)
            #pragma unroll
            for (int j = 0; j < 16; j++) {
                float s = p[j];
                s += __shfl_xor_sync(0xffffffffu, s, 4);
                s += __shfl_xor_sync(0xffffffffu, s, 8);
                s += __shfl_xor_sync(0xffffffffu, s, 16);
                if ((tid & 31) < 4) red[warp][qd*16 + j] = s;
            }
        }
        __syncthreads();

        // PV accumulate: attn[64,64] += P[64,64] @ V[64,64]
        #pragma unroll
        for (int kk = 0; kk < 64; kk += 16) {
            HFragA a; wmma::load_matrix_sync(a, &Ps[wm*16][kk], 72);
            HFragBr b0; wmma::load_matrix_sync(b0, &Vs[kk][wn*32], 72);
            wmma::mma_sync(pv0, a, b0, pv0);
            HFragBr b1; wmma::load_matrix_sync(b1, &Vs[kk][wn*32 + 16], 72);
            wmma::mma_sync(pv1, a, b1, pv1);
        }

        // electrode final: 64 threads, one column each
        if (tid < 64) {
            float s = 0.f;
            #pragma unroll
            for (int r = 0; r < 8; r++) s += red[r][tid];
            atomicAdd(&elect[b * S_ + t0 + tid], s * esc);
        }
        __syncthreads();
    }

    // epilogue: stage PV (already normalized), write concat [b, s, h*64 + d]
    wmma::store_matrix_sync(&St[wm*16][wn*32],      pv0, 68, wmma::mem_row_major);
    wmma::store_matrix_sync(&St[wm*16][wn*32 + 16], pv1, 68, wmma::mem_row_major);
    __syncthreads();
    #pragma unroll
    for (int i = 0; i < 4; i++) {
        const int vi = tid + i * 256;
        const int r = vi >> 4, c = (vi & 15) * 4;
        float4 s = *(float4*)&St[r][c];
        st_half4(&g_concat[((size_t)(b * S_ + m0 + r)) * E_ + h * DH_ + c], s);
    }
}

// ---------------------------------------------------------------------------
// K3: O-projection (fp16 HMMA).  x[m,n] = sum_k concat[m,k]*Wo[n,k] + bo[n]
// grid (E/64, BS/64), block 256.  Tile 64x64, K-chunk 64.
// ---------------------------------------------------------------------------
__global__ void oproj_tc_kernel(const float* __restrict__ Wo, const float* __restrict__ bo,
                                float* __restrict__ x) {
    const int n0 = blockIdx.x * 64, m0 = blockIdx.y * 64;

    __shared__ __align__(16) unsigned char smbuf[18432];
    __half (*As)[72] = (__half(*)[72])smbuf;                // 64x64 half [m][k]
    __half (*Bs)[72] = (__half(*)[72])(smbuf + 9216);       // 64x64 half [n][k]
    float  (*St)[68] = (float(*)[68])smbuf;                 // stage (aliases)

    const int tid  = threadIdx.x;
    const int warp = tid >> 5;
    const int wm = warp >> 1, wn = warp & 1;

    HFragC c0, c1;
    wmma::fill_fragment(c0, 0.f);
    wmma::fill_fragment(c1, 0.f);

    for (int k0 = 0; k0 < E_; k0 += 64) {
        #pragma unroll
        for (int i = 0; i < 4; i++) {
            const int vi = tid + i * 256;
            const int r = vi >> 4, c = (vi & 15) * 4;
            *(uint2*)&As[r][c] = *(const uint2*)&g_concat[(size_t)(m0 + r) * E_ + k0 + c];
            st_half4(&Bs[r][c], *(const float4*)&Wo[(size_t)(n0 + r) * E_ + k0 + c]);
        }
        __syncthreads();
        #pragma unroll
        for (int kk = 0; kk < 64; kk += 16) {
            HFragA a; wmma::load_matrix_sync(a, &As[wm*16][kk], 72);
            HFragBc b0; wmma::load_matrix_sync(b0, &Bs[wn*32][kk], 72);
            wmma::mma_sync(c0, a, b0, c0);
            HFragBc b1; wmma::load_matrix_sync(b1, &Bs[wn*32 + 16][kk], 72);
            wmma::mma_sync(c1, a, b1, c1);
        }
        __syncthreads();
    }
    wmma::store_matrix_sync(&St[wm*16][wn*32],      c0, 68, wmma::mem_row_major);
    wmma::store_matrix_sync(&St[wm*16][wn*32 + 16], c1, 68, wmma::mem_row_major);
    __syncthreads();
    #pragma unroll
    for (int i = 0; i < 4; i++) {
        const int vi = tid + i * 256;
        const int r = vi >> 4, c = (vi & 15) * 4;
        float4 s = *(float4*)&St[r][c];
        s.x += bo[n0 + c]; s.y += bo[n0 + c + 1]; s.z += bo[n0 + c + 2]; s.w += bo[n0 + c + 3];
        *(float4*)&x[(size_t)(m0 + r) * E_ + n0 + c] = s;
    }
}

// ---------------------------------------------------------------------------
__global__ void zero_elect_kernel(float* __restrict__ elect) {
    const int i = blockIdx.x * blockDim.x + threadIdx.x;
    if (i < B_ * S_) elect[i] = 0.f;
}

// ---------------------------------------------------------------------------
extern "C" void kernel_launch(void* const* d_in, const int* in_sizes, int n_in,
                              void* d_out, int out_size) {
    const float* hs = (const float*)d_in[0];
    const float* Wq = (const float*)d_in[1];
    const float* bq = (const float*)d_in[2];
    const float* Wk = (const float*)d_in[3];
    const float* bk = (const float*)d_in[4];
    const float* Wv = (const float*)d_in[5];
    const float* bv = (const float*)d_in[6];
    const float* Wo = (const float*)d_in[7];
    const float* bo = (const float*)d_in[8];

    float* out   = (float*)d_out;
    float* x     = out;                                        // [B,S,E]
    float* wts   = out + (size_t)B_ * S_ * E_;                 // [H,B,S,S]
    float* elect = wts + (size_t)H_ * B_ * S_ * S_;            // [B,S]

    zero_elect_kernel<<<(B_*S_ + 255)/256, 256>>>(elect);
    qkv_tc_kernel<<<dim3(BS_/128, H_), 512>>>(hs, Wq, bq, Wk, bk, Wv, bv);
    attn_fused_kernel<<<dim3(S_/64, H_*B_), 256>>>(wts, elect);
    oproj_tc_kernel<<<dim3(E_/64, BS_/64), 256>>>(Wo, bo, x);
}

// round 17
// speedup vs baseline: 1.0464x; 1.0464x over previous
#include <cuda_runtime.h>
#include <cuda_fp16.h>
#include <mma.h>

using namespace nvcuda;

#define B_  4
#define S_  2048
#define E_  1024
#define H_  16
#define DH_ 64
#define BS_ (B_*S_)   // 8192

// Scratch (allocation-free rule: __device__ globals)
__device__ __half g_q[H_*BS_*DH_];       // Q pre-scaled by 1/8
__device__ __half g_k[H_*BS_*DH_];
__device__ __half g_v[H_*BS_*DH_];
__device__ __half g_concat[BS_*E_];      // [b,s, h*64+d]

typedef wmma::fragment<wmma::matrix_a, 16,16,16, __half, wmma::row_major> HFragA;
typedef wmma::fragment<wmma::matrix_b, 16,16,16, __half, wmma::col_major> HFragBc;
typedef wmma::fragment<wmma::matrix_b, 16,16,16, __half, wmma::row_major> HFragBr;
typedef wmma::fragment<wmma::accumulator, 16,16,16, float> HFragC;

__device__ __forceinline__ void st_half4(__half* dst, float4 v) {
    *(half2*)dst       = __floats2half2_rn(v.x, v.y);
    *(half2*)(dst + 2) = __floats2half2_rn(v.z, v.w);
}

// ---------------------------------------------------------------------------
// K1: merged QKV projection (fp16 HMMA).  One block computes the 64x64 q,k,v
// tiles for one (m-tile, head): hs tile loaded ONCE for all three outputs.
// grid (BS/64, H), block 256.  K-chunk 64.   [round-15 proven config]
// ---------------------------------------------------------------------------
__global__ void qkv_tc_kernel(const float* __restrict__ hs,
                              const float* __restrict__ Wq, const float* __restrict__ bq,
                              const float* __restrict__ Wk, const float* __restrict__ bk,
                              const float* __restrict__ Wv, const float* __restrict__ bv) {
    const int h  = blockIdx.y;
    const int m0 = blockIdx.x * 64;
    const float* Wz[3] = { Wq + (size_t)h * E_ * DH_,
                           Wk + (size_t)h * E_ * DH_,
                           Wv + (size_t)h * E_ * DH_ };
    const float* bz[3] = { bq + h * DH_, bk + h * DH_, bv + h * DH_ };
    __half* oz[3] = { g_q + (size_t)h * BS_ * DH_ + (size_t)m0 * DH_,
                      g_k + (size_t)h * BS_ * DH_ + (size_t)m0 * DH_,
                      g_v + (size_t)h * BS_ * DH_ + (size_t)m0 * DH_ };

    // [0,9216) As half[64][72]; [9216 + z*9216) Bs[z]; St float[64][68] aliases 0
    __shared__ __align__(16) unsigned char smbuf[36864];
    __half (*As)[72] = (__half(*)[72])smbuf;
    float  (*St)[68] = (float(*)[68])smbuf;

    const int tid  = threadIdx.x;
    const int warp = tid >> 5;
    const int wm = warp >> 1, wn = warp & 1;

    HFragC acc[3][2];
    #pragma unroll
    for (int z = 0; z < 3; z++) {
        wmma::fill_fragment(acc[z][0], 0.f);
        wmma::fill_fragment(acc[z][1], 0.f);
    }

    for (int k0 = 0; k0 < E_; k0 += 64) {
        #pragma unroll
        for (int i = 0; i < 4; i++) {
            const int vi = tid + i * 256;
            const int r = vi >> 4, c = (vi & 15) * 4;
            st_half4(&As[r][c], *(const float4*)&hs[(size_t)(m0 + r) * E_ + k0 + c]);
            #pragma unroll
            for (int z = 0; z < 3; z++) {
                __half (*Bs)[72] = (__half(*)[72])(smbuf + 9216 + z * 9216);
                st_half4(&Bs[r][c], *(const float4*)&Wz[z][(size_t)(k0 + r) * DH_ + c]);
            }
        }
        __syncthreads();
        #pragma unroll
        for (int kk = 0; kk < 64; kk += 16) {
            HFragA a; wmma::load_matrix_sync(a, &As[wm*16][kk], 72);
            #pragma unroll
            for (int z = 0; z < 3; z++) {
                __half (*Bs)[72] = (__half(*)[72])(smbuf + 9216 + z * 9216);
                HFragBr b0; wmma::load_matrix_sync(b0, &Bs[kk][wn*32], 72);
                wmma::mma_sync(acc[z][0], a, b0, acc[z][0]);
                HFragBr b1; wmma::load_matrix_sync(b1, &Bs[kk][wn*32 + 16], 72);
                wmma::mma_sync(acc[z][1], a, b1, acc[z][1]);
            }
        }
        __syncthreads();
    }
    #pragma unroll
    for (int z = 0; z < 3; z++) {
        const float out_scale = (z == 0) ? 0.125f : 1.0f;
        wmma::store_matrix_sync(&St[wm*16][wn*32],      acc[z][0], 68, wmma::mem_row_major);
        wmma::store_matrix_sync(&St[wm*16][wn*32 + 16], acc[z][1], 68, wmma::mem_row_major);
        __syncthreads();
        const float* bias = bz[z];
        #pragma unroll
        for (int i = 0; i < 4; i++) {
            const int vi = tid + i * 256;
            const int r = vi >> 4, c = (vi & 15) * 4;
            float4 s = *(float4*)&St[r][c];
            s.x = (s.x + bias[c])   * out_scale;
            s.y = (s.y + bias[c+1]) * out_scale;
            s.z = (s.z + bias[c+2]) * out_scale;
            s.w = (s.w + bias[c+3]) * out_scale;
            st_half4(&oz[z][(size_t)r * DH_ + c], s);
        }
        __syncthreads();
    }
}

// ---------------------------------------------------------------------------
// K2: two-pass attention (fp16 HMMA).  [round-15 proven config, untouched]
// Pass 1: stream K, S = QK^T, row-sum of exp(S) -> 1/l.
// Pass 2: recompute S, write NORMALIZED exp(S)/l (fp32) to weights,
//         electrode column sums (warp-0 atomics), PV accumulate.
// grid (S/64, H*B), block 256.
// ---------------------------------------------------------------------------
__global__ void attn_fused_kernel(float* __restrict__ wts, float* __restrict__ elect) {
    const int hb = blockIdx.y;
    const int h = hb / B_, b = hb % B_;
    const int m0 = blockIdx.x * 64;
    const __half* q = g_q + ((size_t)h * BS_ + (size_t)b * S_) * DH_;
    const __half* k = g_k + ((size_t)h * BS_ + (size_t)b * S_) * DH_;
    const __half* v = g_v + ((size_t)h * BS_ + (size_t)b * S_) * DH_;
    float* w = wts + (size_t)hb * S_ * S_;

    __shared__ __align__(16) unsigned char smbuf[23552];
    __half (*Qs)[72] = (__half(*)[72])smbuf;
    float  (*Ss)[36] = (float(*)[36])smbuf;
    __half (*Ks)[72] = (__half(*)[72])(smbuf + 9216);
    __half (*Vs)[72] = (__half(*)[72])(smbuf + 13824);
    __half (*Ps)[40] = (__half(*)[40])(smbuf + 18432);
    float  (*St)[68] = (float(*)[68])smbuf;
    __shared__ float l_s[64];

    const int tid  = threadIdx.x;
    const int warp = tid >> 5;
    const int wm = warp >> 1, wn = warp & 1;

    #pragma unroll
    for (int i = 0; i < 4; i++) {
        const int vi = tid + i * 256;
        const int r = vi >> 4, c = (vi & 15) * 4;
        *(uint2*)&Qs[r][c] = *(const uint2*)&q[(size_t)(m0 + r) * DH_ + c];
    }
    __syncthreads();

    HFragA qa[4];
    #pragma unroll
    for (int kk = 0; kk < 4; kk++)
        wmma::load_matrix_sync(qa[kk], &Qs[wm*16][kk*16], 72);
    __syncthreads();   // Qs free -> Ss

    const int row = tid >> 2, qd = tid & 3;   // 64 rows x 4 lanes
    float lsum = 0.f;

    // ===================== pass 1: row sums of exp(S) =====================
    for (int t0 = 0; t0 < S_; t0 += 32) {
        #pragma unroll
        for (int i = 0; i < 2; i++) {
            const int vi = tid + i * 256;
            const int r = vi >> 4, c = (vi & 15) * 4;
            *(uint2*)&Ks[r][c] = *(const uint2*)&k[(size_t)(t0 + r) * DH_ + c];
        }
        __syncthreads();

        HFragC c0;
        wmma::fill_fragment(c0, 0.f);
        #pragma unroll
        for (int kk = 0; kk < 4; kk++) {
            HFragBc bb; wmma::load_matrix_sync(bb, &Ks[wn*16][kk*16], 72);
            wmma::mma_sync(c0, qa[kk], bb, c0);
        }
        wmma::store_matrix_sync(&Ss[wm*16][wn*16], c0, 36, wmma::mem_row_major);
        __syncthreads();

        #pragma unroll
        for (int j = 0; j < 8; j++) lsum += __expf(Ss[row][qd*8 + j]);
        __syncthreads();
    }
    lsum += __shfl_xor_sync(0xffffffffu, lsum, 1);
    lsum += __shfl_xor_sync(0xffffffffu, lsum, 2);
    if (qd == 0) l_s[row] = 1.0f / lsum;
    __syncthreads();
    const float il = l_s[row];

    // ===================== pass 2: normalized P + electrode + PV ==========
    HFragC pv0, pv1;
    wmma::fill_fragment(pv0, 0.f);
    wmma::fill_fragment(pv1, 0.f);

    const float esc = 1.0f / (H_ * S_);

    for (int t0 = 0; t0 < S_; t0 += 32) {
        #pragma unroll
        for (int i = 0; i < 2; i++) {
            const int vi = tid + i * 256;
            const int r = vi >> 4, c = (vi & 15) * 4;
            *(uint2*)&Ks[r][c] = *(const uint2*)&k[(size_t)(t0 + r) * DH_ + c];
            *(uint2*)&Vs[r][c] = *(const uint2*)&v[(size_t)(t0 + r) * DH_ + c];
        }
        __syncthreads();

        HFragC c0;
        wmma::fill_fragment(c0, 0.f);
        #pragma unroll
        for (int kk = 0; kk < 4; kk++) {
            HFragBc bb; wmma::load_matrix_sync(bb, &Ks[wn*16][kk*16], 72);
            wmma::mma_sync(c0, qa[kk], bb, c0);
        }
        wmma::store_matrix_sync(&Ss[wm*16][wn*16], c0, 36, wmma::mem_row_major);
        __syncthreads();

        // normalized p: write fp32 to weights, half to Ps
        {
            float p[8];
            #pragma unroll
            for (int j = 0; j < 8; j++) {
                p[j] = __expf(Ss[row][qd*8 + j]) * il;
                Ps[row][qd*8 + j] = __float2half_rn(p[j]);
            }
            float* wr = &w[(size_t)(m0 + row) * S_ + t0 + qd*8];
            *(float4*)wr       = make_float4(p[0], p[1], p[2], p[3]);
            *(float4*)(wr + 4) = make_float4(p[4], p[5], p[6], p[7]);
        }
        __syncthreads();

        // PV accumulate: attn[64,64] += P[64,32] @ V[32,64]
        #pragma unroll
        for (int kk = 0; kk < 32; kk += 16) {
            HFragA a; wmma::load_matrix_sync(a, &Ps[wm*16][kk], 40);
            HFragBr b0; wmma::load_matrix_sync(b0, &Vs[kk][wn*32], 72);
            wmma::mma_sync(pv0, a, b0, pv0);
            HFragBr b1; wmma::load_matrix_sync(b1, &Vs[kk][wn*32 + 16], 72);
            wmma::mma_sync(pv1, a, b1, pv1);
        }

        // electrode: warp 0 sums columns of Ps (64 rows x 32 cols)
        if (tid < 32) {
            float s = 0.f;
            #pragma unroll 8
            for (int r = 0; r < 64; r++) s += __half2float(Ps[r][tid]);
            atomicAdd(&elect[b * S_ + t0 + tid], s * esc);
        }
        __syncthreads();
    }

    // epilogue: stage PV (already normalized), write concat [b, s, h*64 + d]
    wmma::store_matrix_sync(&St[wm*16][wn*32],      pv0, 68, wmma::mem_row_major);
    wmma::store_matrix_sync(&St[wm*16][wn*32 + 16], pv1, 68, wmma::mem_row_major);
    __syncthreads();
    #pragma unroll
    for (int i = 0; i < 4; i++) {
        const int vi = tid + i * 256;
        const int r = vi >> 4, c = (vi & 15) * 4;
        float4 s = *(float4*)&St[r][c];
        st_half4(&g_concat[((size_t)(b * S_ + m0 + r)) * E_ + h * DH_ + c], s);
    }
}

// ---------------------------------------------------------------------------
// K3: O-projection (fp16 HMMA) — 4 warps, 32x32 warp tile (2x2 C frags):
// fragment-loads per mma drops 1.5 -> 1.0 (attacks the measured 77% L1 pipe).
// x[m,n] = sum_k concat[m,k]*Wo[n,k] + bo[n]
// grid (E/64, BS/64), block 128.  Tile 64x64, K-chunk 64.
// ---------------------------------------------------------------------------
__global__ void oproj_tc_kernel(const float* __restrict__ Wo, const float* __restrict__ bo,
                                float* __restrict__ x) {
    const int n0 = blockIdx.x * 64, m0 = blockIdx.y * 64;

    __shared__ __align__(16) unsigned char smbuf[18432];
    __half (*As)[72] = (__half(*)[72])smbuf;                // 64x64 half [m][k]
    __half (*Bs)[72] = (__half(*)[72])(smbuf + 9216);       // 64x64 half [n][k]
    float  (*St)[68] = (float(*)[68])smbuf;                 // stage (aliases)

    const int tid  = threadIdx.x;
    const int warp = tid >> 5;
    const int wm = warp >> 1, wn = warp & 1;                // 2x2 warps of 32x32

    HFragC c00, c01, c10, c11;
    wmma::fill_fragment(c00, 0.f); wmma::fill_fragment(c01, 0.f);
    wmma::fill_fragment(c10, 0.f); wmma::fill_fragment(c11, 0.f);

    for (int k0 = 0; k0 < E_; k0 += 64) {
        #pragma unroll
        for (int i = 0; i < 8; i++) {                       // 1024 float4 each
            const int vi = tid + i * 128;
            const int r = vi >> 4, c = (vi & 15) * 4;
            *(uint2*)&As[r][c] = *(const uint2*)&g_concat[(size_t)(m0 + r) * E_ + k0 + c];
            st_half4(&Bs[r][c], *(const float4*)&Wo[(size_t)(n0 + r) * E_ + k0 + c]);
        }
        __syncthreads();
        #pragma unroll
        for (int kk = 0; kk < 64; kk += 16) {
            HFragA a0, a1; HFragBc b0, b1;
            wmma::load_matrix_sync(a0, &As[wm*32][kk], 72);
            wmma::load_matrix_sync(a1, &As[wm*32 + 16][kk], 72);
            wmma::load_matrix_sync(b0, &Bs[wn*32][kk], 72);
            wmma::load_matrix_sync(b1, &Bs[wn*32 + 16][kk], 72);
            wmma::mma_sync(c00, a0, b0, c00);
            wmma::mma_sync(c01, a0, b1, c01);
            wmma::mma_sync(c10, a1, b0, c10);
            wmma::mma_sync(c11, a1, b1, c11);
        }
        __syncthreads();
    }
    wmma::store_matrix_sync(&St[wm*32][wn*32],           c00, 68, wmma::mem_row_major);
    wmma::store_matrix_sync(&St[wm*32][wn*32 + 16],      c01, 68, wmma::mem_row_major);
    wmma::store_matrix_sync(&St[wm*32 + 16][wn*32],      c10, 68, wmma::mem_row_major);
    wmma::store_matrix_sync(&St[wm*32 + 16][wn*32 + 16], c11, 68, wmma::mem_row_major);
    __syncthreads();
    #pragma unroll
    for (int i = 0; i < 8; i++) {
        const int vi = tid + i * 128;
        const int r = vi >> 4, c = (vi & 15) * 4;
        float4 s = *(float4*)&St[r][c];
        s.x += bo[n0 + c]; s.y += bo[n0 + c + 1]; s.z += bo[n0 + c + 2]; s.w += bo[n0 + c + 3];
        *(float4*)&x[(size_t)(m0 + r) * E_ + n0 + c] = s;
    }
}

// ---------------------------------------------------------------------------
__global__ void zero_elect_kernel(float* __restrict__ elect) {
    const int i = blockIdx.x * blockDim.x + threadIdx.x;
    if (i < B_ * S_) elect[i] = 0.f;
}

// ---------------------------------------------------------------------------
extern "C" void kernel_launch(void* const* d_in, const int* in_sizes, int n_in,
                              void* d_out, int out_size) {
    const float* hs = (const float*)d_in[0];
    const float* Wq = (const float*)d_in[1];
    const float* bq = (const float*)d_in[2];
    const float* Wk = (const float*)d_in[3];
    const float* bk = (const float*)d_in[4];
    const float* Wv = (const float*)d_in[5];
    const float* bv = (const float*)d_in[6];
    const float* Wo = (const float*)d_in[7];
    const float* bo = (const float*)d_in[8];

    float* out   = (float*)d_out;
    float* x     = out;                                        // [B,S,E]
    float* wts   = out + (size_t)B_ * S_ * E_;                 // [H,B,S,S]
    float* elect = wts + (size_t)H_ * B_ * S_ * S_;            // [B,S]

    zero_elect_kernel<<<(B_*S_ + 255)/256, 256>>>(elect);
    qkv_tc_kernel<<<dim3(BS_/64, H_), 256>>>(hs, Wq, bq, Wk, bk, Wv, bv);
    attn_fused_kernel<<<dim3(S_/64, H_*B_), 256>>>(wts, elect);
    oproj_tc_kernel<<<dim3(E_/64, BS_/64), 128>>>(Wo, bo, x);
}